// round 3
// baseline (speedup 1.0000x reference)
#include <cuda_runtime.h>

#define NN 100000
#define NE 3200000
#define IND 128
#define H1 32
#define H2 16
#define NG 512

// ---- device-global scratch (no allocs allowed) ----
__device__ __align__(16) float g_h1s[NN * H1];   // dinv-scaled x@W1
__device__ __align__(16) float g_acc1[NN * H1];  // scatter accumulator L1
__device__ __align__(16) float g_h2s[NN * H2];   // dinv-scaled relu1@W2
__device__ __align__(16) float g_acc2[NN * H2];  // scatter accumulator L2
__device__ __align__(16) float g_pool[NG * H2];  // per-graph sums
__device__ float g_cnt[NG];
__device__ float g_dinv[NN];
__device__ int   g_deg[NN];

// ---- zero all accumulators ----
__global__ void k_zero() {
    int i = blockIdx.x * blockDim.x + threadIdx.x;
    if (i < NN * H1) g_acc1[i] = 0.f;
    if (i < NN * H2) g_acc2[i] = 0.f;
    if (i < NN)      g_deg[i]  = 0;
    if (i < NG * H2) g_pool[i] = 0.f;
    if (i < NG)      g_cnt[i]  = 0.f;
}

// ---- degree count (edge_index is int32: JAX x64 is disabled by default) ----
__global__ void k_deg(const int* __restrict__ ei) {
    int i = blockIdx.x * blockDim.x + threadIdx.x;
    if (i >= NE) return;
    int d = ei[NE + i];
    atomicAdd(&g_deg[d], 1);
}

__global__ void k_dinv() {
    int i = blockIdx.x * blockDim.x + threadIdx.x;
    if (i < NN) g_dinv[i] = rsqrtf((float)(g_deg[i] + 1));
}

// ---- h1s = dinv * (x @ W1), thread-per-node, W1 in smem ----
__global__ void k_gemm1(const float* __restrict__ x, const float* __restrict__ W1) {
    __shared__ float sW[IND * H1];
    for (int i = threadIdx.x; i < IND * H1; i += blockDim.x) sW[i] = W1[i];
    __syncthreads();
    int n = blockIdx.x * blockDim.x + threadIdx.x;
    if (n >= NN) return;
    float acc[H1];
#pragma unroll
    for (int j = 0; j < H1; j++) acc[j] = 0.f;
    const float4* xr = (const float4*)(x + (size_t)n * IND);
#pragma unroll 4
    for (int k4 = 0; k4 < IND / 4; k4++) {
        float4 xv = __ldg(&xr[k4]);
#pragma unroll
        for (int q = 0; q < 4; q++) {
            float xc = (q == 0) ? xv.x : (q == 1) ? xv.y : (q == 2) ? xv.z : xv.w;
            const float4* wr = (const float4*)&sW[(k4 * 4 + q) * H1];
#pragma unroll
            for (int j4 = 0; j4 < H1 / 4; j4++) {
                float4 w = wr[j4];
                acc[j4 * 4 + 0] += xc * w.x;
                acc[j4 * 4 + 1] += xc * w.y;
                acc[j4 * 4 + 2] += xc * w.z;
                acc[j4 * 4 + 3] += xc * w.w;
            }
        }
    }
    float s = g_dinv[n];
    float4* o = (float4*)&g_h1s[n * H1];
#pragma unroll
    for (int j4 = 0; j4 < H1 / 4; j4++)
        o[j4] = make_float4(acc[j4 * 4 + 0] * s, acc[j4 * 4 + 1] * s,
                            acc[j4 * 4 + 2] * s, acc[j4 * 4 + 3] * s);
}

// ---- scatter layer1: 8 lanes per edge, one 128B line gathered + vector RED ----
__global__ void k_scat1(const int* __restrict__ ei) {
    int t = blockIdx.x * blockDim.x + threadIdx.x;
    int e = t >> 3;
    if (e >= NE) return;
    int sub = t & 7;
    int s = ei[e];
    int d = ei[NE + e];
    float4 v = *(const float4*)&g_h1s[s * H1 + sub * 4];
    float* p = &g_acc1[d * H1 + sub * 4];
    asm volatile("red.global.add.v4.f32 [%0], {%1, %2, %3, %4};"
                 :: "l"(p), "f"(v.x), "f"(v.y), "f"(v.z), "f"(v.w) : "memory");
}

// ---- finalize layer1 (norm + bias + relu) fused with GEMM2 + dinv scale ----
__global__ void k_fin1(const float* __restrict__ b1, const float* __restrict__ W2) {
    __shared__ float sW[H1 * H2];
    __shared__ float sb[H1];
    for (int i = threadIdx.x; i < H1 * H2; i += blockDim.x) sW[i] = W2[i];
    if (threadIdx.x < H1) sb[threadIdx.x] = b1[threadIdx.x];
    __syncthreads();
    int n = blockIdx.x * blockDim.x + threadIdx.x;
    if (n >= NN) return;
    float dv = g_dinv[n];
    float v[H1];
    const float4* a = (const float4*)&g_acc1[n * H1];
    const float4* h = (const float4*)&g_h1s[n * H1];
#pragma unroll
    for (int j4 = 0; j4 < H1 / 4; j4++) {
        float4 av = a[j4], hv = h[j4];
        v[j4 * 4 + 0] = fmaxf(dv * (av.x + hv.x) + sb[j4 * 4 + 0], 0.f);
        v[j4 * 4 + 1] = fmaxf(dv * (av.y + hv.y) + sb[j4 * 4 + 1], 0.f);
        v[j4 * 4 + 2] = fmaxf(dv * (av.z + hv.z) + sb[j4 * 4 + 2], 0.f);
        v[j4 * 4 + 3] = fmaxf(dv * (av.w + hv.w) + sb[j4 * 4 + 3], 0.f);
    }
    float acc[H2];
#pragma unroll
    for (int l = 0; l < H2; l++) acc[l] = 0.f;
#pragma unroll
    for (int j = 0; j < H1; j++) {
        float vj = v[j];
        const float4* wr = (const float4*)&sW[j * H2];
#pragma unroll
        for (int l4 = 0; l4 < H2 / 4; l4++) {
            float4 w = wr[l4];
            acc[l4 * 4 + 0] += vj * w.x;
            acc[l4 * 4 + 1] += vj * w.y;
            acc[l4 * 4 + 2] += vj * w.z;
            acc[l4 * 4 + 3] += vj * w.w;
        }
    }
    float4* o = (float4*)&g_h2s[n * H2];
#pragma unroll
    for (int l4 = 0; l4 < H2 / 4; l4++)
        o[l4] = make_float4(acc[l4 * 4 + 0] * dv, acc[l4 * 4 + 1] * dv,
                            acc[l4 * 4 + 2] * dv, acc[l4 * 4 + 3] * dv);
}

// ---- scatter layer2: 4 lanes per edge ----
__global__ void k_scat2(const int* __restrict__ ei) {
    int t = blockIdx.x * blockDim.x + threadIdx.x;
    int e = t >> 2;
    if (e >= NE) return;
    int sub = t & 3;
    int s = ei[e];
    int d = ei[NE + e];
    float4 v = *(const float4*)&g_h2s[s * H2 + sub * 4];
    float* p = &g_acc2[d * H2 + sub * 4];
    asm volatile("red.global.add.v4.f32 [%0], {%1, %2, %3, %4};"
                 :: "l"(p), "f"(v.x), "f"(v.y), "f"(v.z), "f"(v.w) : "memory");
}

// ---- finalize layer2 + mean-pool scatter ----
__global__ void k_fin2(const float* __restrict__ b2, const int* __restrict__ batch) {
    __shared__ float sb[H2];
    if (threadIdx.x < H2) sb[threadIdx.x] = b2[threadIdx.x];
    __syncthreads();
    int n = blockIdx.x * blockDim.x + threadIdx.x;
    if (n < NN) {
        float dv = g_dinv[n];
        int g = batch[n];
        const float4* a = (const float4*)&g_acc2[n * H2];
        const float4* h = (const float4*)&g_h2s[n * H2];
#pragma unroll
        for (int l4 = 0; l4 < H2 / 4; l4++) {
            float4 av = a[l4], hv = h[l4];
            float4 o;
            o.x = fmaxf(dv * (av.x + hv.x) + sb[l4 * 4 + 0], 0.f);
            o.y = fmaxf(dv * (av.y + hv.y) + sb[l4 * 4 + 1], 0.f);
            o.z = fmaxf(dv * (av.z + hv.z) + sb[l4 * 4 + 2], 0.f);
            o.w = fmaxf(dv * (av.w + hv.w) + sb[l4 * 4 + 3], 0.f);
            float* p = &g_pool[g * H2 + l4 * 4];
            asm volatile("red.global.add.v4.f32 [%0], {%1, %2, %3, %4};"
                         :: "l"(p), "f"(o.x), "f"(o.y), "f"(o.z), "f"(o.w) : "memory");
        }
        // warp-aggregated counts (batch is sorted -> near-uniform per warp)
        unsigned am = __activemask();
        unsigned mk = __match_any_sync(am, g);
        if ((int)(threadIdx.x & 31) == (__ffs(mk) - 1))
            atomicAdd(&g_cnt[g], (float)__popc(mk));
    }
}

// ---- final: mean + W3 + b3 ----
__global__ void k_final(const float* __restrict__ W3, const float* __restrict__ b3,
                        float* __restrict__ out) {
    int g = blockIdx.x * blockDim.x + threadIdx.x;
    if (g >= NG) return;
    float inv = 1.f / fmaxf(g_cnt[g], 1.f);
    float acc = 0.f;
#pragma unroll
    for (int l = 0; l < H2; l++) acc += g_pool[g * H2 + l] * __ldg(&W3[l]);
    out[g] = acc * inv + __ldg(&b3[0]);
}

extern "C" void kernel_launch(void* const* d_in, const int* in_sizes, int n_in,
                              void* d_out, int out_size) {
    const float* x     = (const float*)d_in[0];
    const int*   ei    = (const int*)d_in[1];    // int32 (JAX x64 disabled)
    const int*   batch = (const int*)d_in[2];    // int32
    const float* W1    = (const float*)d_in[3];
    const float* b1    = (const float*)d_in[4];
    const float* W2    = (const float*)d_in[5];
    const float* b2    = (const float*)d_in[6];
    const float* W3    = (const float*)d_in[7];
    const float* b3    = (const float*)d_in[8];
    float* out = (float*)d_out;

    k_zero <<<(NN * H1 + 255) / 256, 256>>>();
    k_deg  <<<(NE + 255) / 256, 256>>>(ei);
    k_dinv <<<(NN + 255) / 256, 256>>>();
    k_gemm1<<<(NN + 255) / 256, 256>>>(x, W1);
    k_scat1<<<((long long)NE * 8 + 255) / 256, 256>>>(ei);
    k_fin1 <<<(NN + 255) / 256, 256>>>(b1, W2);
    k_scat2<<<((long long)NE * 4 + 255) / 256, 256>>>(ei);
    k_fin2 <<<(NN + 255) / 256, 256>>>(b2, batch);
    k_final<<<(NG + 255) / 256, 256>>>(W3, b3, out);
}